// round 15
// baseline (speedup 1.0000x reference)
#include <cuda_runtime.h>
#include <cuda.h>
#include <cuda_fp16.h>
#include <cstdint>

#define BATCH 512
#define SEQLEN 512
#define INSZ 64
#define RES 1024
#define OUTSZ 64

// ---------------- static device buffers (no allocation allowed) -------------
__device__ float g_state[BATCH * RES];              // fp32 state, in-place
__device__ __half g_shi[2][BATCH * RES];            // state hi (fp16), ping-pong
__device__ __half g_slo[2][BATCH * RES];            // state lo (fp16), ping-pong
__device__ __half g_w16[RES * RES];                 // W_res in fp16
__device__ __half g_win16[INSZ * RES];              // W_in in fp16
__device__ __half g_xhi[BATCH * SEQLEN * INSZ];     // input hi
__device__ __half g_xlo[BATCH * SEQLEN * INSZ];     // input lo

struct TMaps {
    CUtensorMap shi[2];   // fp16, box {64,32}
    CUtensorMap slo[2];   // fp16, box {64,32}
    CUtensorMap w;        // fp16, box {64,64}
    CUtensorMap win;      // fp16, box {64,64}
    CUtensorMap xhi;      // fp16 3D, box {64,1,32}
    CUtensorMap xlo;
    CUtensorMap st;       // fp32, box {64,32}, no swizzle
};

// ---------------- merged prep kernel (ONE launch) ---------------------------
__global__ void prep_kernel(const float* __restrict__ input,
                            const float* __restrict__ Wres,
                            const float* __restrict__ Win) {
    int i = blockIdx.x * blockDim.x + threadIdx.x;
    int stride = gridDim.x * blockDim.x;
    const __half z = __float2half(0.0f);
    for (int k = i; k < BATCH * SEQLEN * INSZ; k += stride) {
        float v = input[k];
        __half h = __float2half(v);
        g_xhi[k] = h;
        g_xlo[k] = __float2half(v - __half2float(h));
        if (k < RES * RES) g_w16[k] = __float2half(Wres[k]);
        if (k < INSZ * RES) g_win16[k] = __float2half(Win[k]);
        if (k < BATCH * RES) {
            g_state[k] = 0.0f;
            g_shi[0][k] = z;
            g_slo[0][k] = z;
        }
    }
}

// ---------------- fast tanh (ex2 + rcp approx; abs err ~1e-6) ---------------
__device__ __forceinline__ float fast_tanhf(float x) {
    float e;
    asm("ex2.approx.f32 %0, %1;" : "=f"(e) : "f"(x * 2.8853900817779268f));
    float r;
    asm("rcp.approx.f32 %0, %1;" : "=f"(r) : "f"(e + 1.0f));
    return fmaf(-2.0f, r, 1.0f);
}

// ---------------- PTX helpers ------------------------------------------------
#define MBARRIER_INIT(addr, cnt) \
    asm volatile("mbarrier.init.shared.b64 [%0], %1;" :: "r"(addr), "r"(cnt) : "memory")

#define MBARRIER_EXPECT_TX(addr, bytes) \
    asm volatile("mbarrier.arrive.expect_tx.shared.b64 _, [%0], %1;" \
                 :: "r"(addr), "r"(bytes) : "memory")

#define MBARRIER_ARRIVE(addr) \
    asm volatile("mbarrier.arrive.shared.b64 _, [%0];" :: "r"(addr) : "memory")

#define MBARRIER_WAIT_PARITY(mbar, par) do {                                   \
    uint32_t _m = (mbar); uint32_t _p = (par); uint32_t _done;                 \
    asm volatile("{\n\t.reg .pred p;\n\t"                                      \
        "mbarrier.try_wait.parity.acquire.cta.shared::cta.b64 p, [%1], %2;\n\t"\
        "selp.b32 %0, 1, 0, p;\n\t}" : "=r"(_done) : "r"(_m), "r"(_p) : "memory"); \
    if (!_done) {                                                              \
        asm volatile("{\n\t.reg .pred P1;\n\tWL_%=:\n\t"                       \
            "mbarrier.try_wait.parity.acquire.cta.shared::cta.b64 P1, [%0], %1, 0x989680;\n\t" \
            "@P1 bra.uni WD_%=;\n\tbra.uni WL_%=;\n\tWD_%=:\n\t}"              \
            :: "r"(_m), "r"(_p) : "memory");                                   \
    }                                                                          \
} while (0)

__device__ __forceinline__ void tma2d(uint32_t dst, const CUtensorMap* m,
                                      int c0, int c1, uint32_t mbar) {
    asm volatile(
        "cp.async.bulk.tensor.2d.shared::cluster.global.tile.mbarrier::complete_tx::bytes "
        "[%0], [%1, {%2, %3}], [%4];"
        :: "r"(dst), "l"(m), "r"(c0), "r"(c1), "r"(mbar) : "memory");
}

__device__ __forceinline__ void tma3d(uint32_t dst, const CUtensorMap* m,
                                      int c0, int c1, int c2, uint32_t mbar) {
    asm volatile(
        "cp.async.bulk.tensor.3d.shared::cluster.global.tile.mbarrier::complete_tx::bytes "
        "[%0], [%1, {%2, %3, %4}], [%5];"
        :: "r"(dst), "l"(m), "r"(c0), "r"(c1), "r"(c2), "r"(mbar) : "memory");
}

// ---------------- step kernel ----------------------------------------------
// Y = Shi@W16 + Slo@W16 + xhi@Win16 + xlo@Win16 (2-product fp16 split).
// r15: replace the per-iteration __syncthreads with consumer-release
// mbarriers (count=4): warps arrive after reading a slot; only the producer
// thread waits for all-consumed before reissuing that slot. Non-producer
// warps flow block-to-block gated only by data arrival -> skew absorbed,
// not synchronized.  Tile BM=32 x BN=64, grid (16,16)=256 CTAs, 128 thr
// (4 warps 2Mx2N, warp tile 16x32), NSLOT=3 ring, smem state epilogue.
#define NIT 9
#define NSLOT 3
#define STAGE_BYTES 32768      // Ahi 8K | Alo 8K | B 16K
#define A_LO_OFF 8192
#define B_OFF    16384
#define ST_OFF   (NSLOT * STAGE_BYTES)          // fp32 state tile 32x64 = 8K
#define SMEM_TOTAL (ST_OFF + 8192)

__device__ __forceinline__ uint32_t sw_off(int row, int colByte) {
    // 128B rows, XOR-swizzled 16B chunks == TMA SW128 atom layout
    return (uint32_t)(row * 128 + ((((colByte >> 4) ^ (row & 7)) << 4) | (colByte & 15)));
}

template<int NKF>
__device__ __forceinline__ void do_block(uint32_t base, int lane, int warpM, int warpN,
                                         float (&acch)[4][4], float (&accl)[4][4]) {
    uint32_t fa[2][2][4];   // [buf][hi/lo][regs]
    uint32_t fb[2][2][4];   // [buf][nh][regs]

    auto ld = [&](int kf, int buf) {
        const int kfl = kf & 3;
        {
            const uint32_t sub = (uint32_t)(kf >> 2) * 4096;   // A half-tiles 4K
            int row = warpM * 16 + (lane & 15);
            int colByte = kfl * 32 + (lane >> 4) * 16;
            uint32_t so = sw_off(row, colByte);
            asm volatile("ldmatrix.sync.aligned.m8n8.x4.shared.b16 {%0,%1,%2,%3}, [%4];"
                : "=r"(fa[buf][0][0]), "=r"(fa[buf][0][1]),
                  "=r"(fa[buf][0][2]), "=r"(fa[buf][0][3])
                : "r"(base + sub + so));
            asm volatile("ldmatrix.sync.aligned.m8n8.x4.shared.b16 {%0,%1,%2,%3}, [%4];"
                : "=r"(fa[buf][1][0]), "=r"(fa[buf][1][1]),
                  "=r"(fa[buf][1][2]), "=r"(fa[buf][1][3])
                : "r"(base + A_LO_OFF + sub + so));
        }
        #pragma unroll
        for (int nh = 0; nh < 2; nh++) {
            const uint32_t sub = (uint32_t)(kf >> 2) * 8192;   // B half-tiles 8K
            int krow = kfl * 16 + (lane & 7) + ((lane >> 3) & 1) * 8;
            int colByte = (warpN * 32 + nh * 16 + (lane >> 4) * 8) * 2;
            asm volatile("ldmatrix.sync.aligned.m8n8.x4.trans.shared.b16 {%0,%1,%2,%3}, [%4];"
                : "=r"(fb[buf][nh][0]), "=r"(fb[buf][nh][1]),
                  "=r"(fb[buf][nh][2]), "=r"(fb[buf][nh][3])
                : "r"(base + B_OFF + sub + sw_off(krow, colByte)));
        }
    };

    ld(0, 0);
    #pragma unroll
    for (int kf = 0; kf < NKF; kf++) {
        const int cur = kf & 1;
        if (kf + 1 < NKF) ld(kf + 1, cur ^ 1);     // prefetch next slice's frags
        #pragma unroll
        for (int j = 0; j < 4; j++) {
            uint32_t b0 = fb[cur][j >> 1][(j & 1) * 2];
            uint32_t b1 = fb[cur][j >> 1][(j & 1) * 2 + 1];
            asm volatile(
                "mma.sync.aligned.m16n8k16.row.col.f32.f16.f16.f32 "
                "{%0,%1,%2,%3}, {%4,%5,%6,%7}, {%8,%9}, {%0,%1,%2,%3};"
                : "+f"(acch[j][0]), "+f"(acch[j][1]), "+f"(acch[j][2]), "+f"(acch[j][3])
                : "r"(fa[cur][0][0]), "r"(fa[cur][0][1]),
                  "r"(fa[cur][0][2]), "r"(fa[cur][0][3]), "r"(b0), "r"(b1));
            asm volatile(
                "mma.sync.aligned.m16n8k16.row.col.f32.f16.f16.f32 "
                "{%0,%1,%2,%3}, {%4,%5,%6,%7}, {%8,%9}, {%0,%1,%2,%3};"
                : "+f"(accl[j][0]), "+f"(accl[j][1]), "+f"(accl[j][2]), "+f"(accl[j][3])
                : "r"(fa[cur][1][0]), "r"(fa[cur][1][1]),
                  "r"(fa[cur][1][2]), "r"(fa[cur][1][3]), "r"(b0), "r"(b1));
        }
    }
}

__global__ __launch_bounds__(128) void step_kernel(
    const __grid_constant__ TMaps tm, int t) {
    extern __shared__ __align__(1024) char smem[];
    // [0..2] data mbars, [3] state mbar, [4..6] consumed mbars
    __shared__ __align__(8) uint64_t s_mbar[NSLOT + 1 + NSLOT];

    const int tid  = threadIdx.x;
    const int lane = tid & 31;
    const int warp = tid >> 5;
    const int warpM = warp & 1;     // 2 warps along M (16 rows each)
    const int warpN = warp >> 1;    // 2 warps along N (32 cols each)
    const int rowBase = blockIdx.y * 32;
    const int colBase = blockIdx.x * 64;
    const int pp = t & 1;

    const uint32_t smem_u32 = (uint32_t)__cvta_generic_to_shared(smem);
    const uint32_t mbar0    = (uint32_t)__cvta_generic_to_shared(s_mbar);
    const uint32_t cons0    = mbar0 + (NSLOT + 1) * 8;

    const CUtensorMap* mShi = &tm.shi[pp];
    const CUtensorMap* mSlo = &tm.slo[pp];

    if (tid == 0) {
        #pragma unroll
        for (int s = 0; s < NSLOT + 1; s++) MBARRIER_INIT(mbar0 + s * 8, 1);
        #pragma unroll
        for (int s = 0; s < NSLOT; s++) MBARRIER_INIT(cons0 + s * 8, 4);
    }
    __syncthreads();   // mbarrier init visibility (only block-wide sync left)

    auto issue = [&](int kk) {
        uint32_t base = smem_u32 + (kk % NSLOT) * STAGE_BYTES;
        uint32_t mb   = mbar0 + (kk % NSLOT) * 8;
        if (kk < 8) {
            int k0 = kk << 7;
            MBARRIER_EXPECT_TX(mb, 32768u);
            tma2d(base,                   mShi, k0,      rowBase, mb);
            tma2d(base + 4096,            mShi, k0 + 64, rowBase, mb);
            tma2d(base + A_LO_OFF,        mSlo, k0,      rowBase, mb);
            tma2d(base + A_LO_OFF + 4096, mSlo, k0 + 64, rowBase, mb);
            tma2d(base + B_OFF,           &tm.w, colBase, k0,      mb);
            tma2d(base + B_OFF + 8192,    &tm.w, colBase, k0 + 64, mb);
        } else {
            MBARRIER_EXPECT_TX(mb, 16384u);
            tma3d(base,            &tm.xhi, 0, t, rowBase, mb);
            tma3d(base + A_LO_OFF, &tm.xlo, 0, t, rowBase, mb);
            tma2d(base + B_OFF,    &tm.win, colBase, 0, mb);
        }
    };

    if (tid == 0) {
        // state tile prefetch (overlaps the whole GEMM)
        MBARRIER_EXPECT_TX(mbar0 + NSLOT * 8, 8192u);
        tma2d(smem_u32 + ST_OFF, &tm.st, colBase, rowBase, mbar0 + NSLOT * 8);
        issue(0); issue(1);
    }

    float acch[4][4], accl[4][4];
    #pragma unroll
    for (int j = 0; j < 4; j++)
        #pragma unroll
        for (int q = 0; q < 4; q++) { acch[j][q] = 0.0f; accl[j][q] = 0.0f; }

    for (int kk = 0; kk < NIT; kk++) {
        // producer: wait all 4 warps consumed stage kk-1 (same slot as kk+2),
        // then reissue. Non-producer warps skip straight to the data wait.
        if (tid == 0 && kk + 2 < NIT) {
            if (kk >= 1)
                MBARRIER_WAIT_PARITY(cons0 + ((kk - 1) % NSLOT) * 8,
                                     (uint32_t)(((kk - 1) / NSLOT) & 1));
            issue(kk + 2);
        }
        MBARRIER_WAIT_PARITY(mbar0 + (kk % NSLOT) * 8, (uint32_t)((kk / NSLOT) & 1));

        uint32_t base = smem_u32 + (kk % NSLOT) * STAGE_BYTES;
        if (kk < 8) do_block<8>(base, lane, warpM, warpN, acch, accl);
        else        do_block<4>(base, lane, warpM, warpN, acch, accl);

        // consumer release: this warp is done reading slot kk%NSLOT
        if (lane == 0) MBARRIER_ARRIVE(cons0 + (kk % NSLOT) * 8);
    }

    // ---- epilogue: combine hi/lo, leaky tanh; state read from smem copy,
    //      write fp32 state + fp16 hi/lo for next step ----
    MBARRIER_WAIT_PARITY(mbar0 + NSLOT * 8, 0u);
    __half* __restrict__ shiN = g_shi[pp ^ 1];
    __half* __restrict__ sloN = g_slo[pp ^ 1];
    #pragma unroll
    for (int j = 0; j < 4; j++)
        #pragma unroll
        for (int h = 0; h < 2; h++) {
            int rloc = warpM * 16 + (lane >> 2) + 8 * h;          // 0..31
            int cloc = warpN * 32 + j * 8 + (lane & 3) * 2;       // 0..62
            int row = rowBase + rloc;
            int col = colBase + cloc;
            long long idx = (long long)row * RES + col;
            float y0 = acch[j][h * 2 + 0] + accl[j][h * 2 + 0];
            float y1 = acch[j][h * 2 + 1] + accl[j][h * 2 + 1];
            float2 sold = *reinterpret_cast<float2*>(
                smem + ST_OFF + rloc * 256 + cloc * 4);
            float n0 = 0.5f * sold.x + 0.5f * fast_tanhf(y0);
            float n1 = 0.5f * sold.y + 0.5f * fast_tanhf(y1);
            *reinterpret_cast<float2*>(&g_state[idx]) = make_float2(n0, n1);
            __half h0 = __float2half(n0);
            __half h1 = __float2half(n1);
            __half2 hv; hv.x = h0; hv.y = h1;
            __half2 lv;
            lv.x = __float2half(n0 - __half2float(h0));
            lv.y = __float2half(n1 - __half2float(h1));
            *reinterpret_cast<__half2*>(&shiN[idx]) = hv;
            *reinterpret_cast<__half2*>(&sloN[idx]) = lv;
        }
}

// ---------------- output GEMM ----------------------------------------------
__global__ __launch_bounds__(64) void output_kernel(
    const float* __restrict__ Wout, float* __restrict__ out) {
    __shared__ float srow[RES];
    const int b = blockIdx.x;
    const int j = threadIdx.x;
    for (int k = j; k < RES; k += 64) srow[k] = g_state[b * RES + k];
    __syncthreads();
    float sum = 0.0f;
    #pragma unroll 8
    for (int k = 0; k < RES; k++)
        sum = fmaf(srow[k], Wout[k * OUTSZ + j], sum);
    out[b * OUTSZ + j] = sum;
}

// ---------------- host: tensormap construction ------------------------------
typedef CUresult (*EncodeFn)(CUtensorMap*, CUtensorMapDataType, cuuint32_t, void*,
                             const cuuint64_t*, const cuuint64_t*, const cuuint32_t*,
                             const cuuint32_t*, CUtensorMapInterleave, CUtensorMapSwizzle,
                             CUtensorMapL2promotion, CUtensorMapFloatOOBfill);

static EncodeFn get_encode_fn() {
    void* p = nullptr;
#if CUDART_VERSION >= 12050
    cudaDriverEntryPointQueryResult st;
    cudaGetDriverEntryPointByVersion("cuTensorMapEncodeTiled", &p, 12000,
                                     cudaEnableDefault, &st);
#else
    cudaDriverEntryPointQueryResult st;
    cudaGetDriverEntryPoint("cuTensorMapEncodeTiled", &p, cudaEnableDefault, &st);
#endif
    return (EncodeFn)p;
}

static void enc2d_box(EncodeFn f, CUtensorMap* m, void* ptr,
                      uint64_t d0, uint64_t d1, uint64_t stride1B,
                      uint32_t b0, uint32_t b1) {
    cuuint64_t dims[2] = {d0, d1};
    cuuint64_t strides[1] = {stride1B};
    cuuint32_t box[2] = {b0, b1};
    cuuint32_t es[2] = {1, 1};
    f(m, CU_TENSOR_MAP_DATA_TYPE_FLOAT16, 2, ptr, dims, strides, box, es,
      CU_TENSOR_MAP_INTERLEAVE_NONE, CU_TENSOR_MAP_SWIZZLE_128B,
      CU_TENSOR_MAP_L2_PROMOTION_L2_128B, CU_TENSOR_MAP_FLOAT_OOB_FILL_NONE);
}

static void enc_state(EncodeFn f, CUtensorMap* m, void* ptr) {
    cuuint64_t dims[2] = {RES, BATCH};
    cuuint64_t strides[1] = {RES * 4ull};
    cuuint32_t box[2] = {64, 32};
    cuuint32_t es[2] = {1, 1};
    f(m, CU_TENSOR_MAP_DATA_TYPE_FLOAT32, 2, ptr, dims, strides, box, es,
      CU_TENSOR_MAP_INTERLEAVE_NONE, CU_TENSOR_MAP_SWIZZLE_NONE,
      CU_TENSOR_MAP_L2_PROMOTION_L2_128B, CU_TENSOR_MAP_FLOAT_OOB_FILL_NONE);
}

static void enc3d_x(EncodeFn f, CUtensorMap* m, void* ptr) {
    cuuint64_t dims[3] = {INSZ, SEQLEN, BATCH};
    cuuint64_t strides[2] = {INSZ * 2ull, (uint64_t)SEQLEN * INSZ * 2ull};
    cuuint32_t box[3] = {64, 1, 32};
    cuuint32_t es[3] = {1, 1, 1};
    f(m, CU_TENSOR_MAP_DATA_TYPE_FLOAT16, 3, ptr, dims, strides, box, es,
      CU_TENSOR_MAP_INTERLEAVE_NONE, CU_TENSOR_MAP_SWIZZLE_128B,
      CU_TENSOR_MAP_L2_PROMOTION_L2_128B, CU_TENSOR_MAP_FLOAT_OOB_FILL_NONE);
}

// ---------------- launch ----------------------------------------------------
extern "C" void kernel_launch(void* const* d_in, const int* in_sizes, int n_in,
                              void* d_out, int out_size) {
    const float* input = (const float*)d_in[0];   // [512,512,64]
    const float* Wres  = (const float*)d_in[1];   // [1024,1024]
    const float* Win   = (const float*)d_in[2];   // [64,1024]
    const float* Wout  = (const float*)d_in[3];   // [1024,64]
    float* out = (float*)d_out;

    void *state, *shi, *slo, *w16, *win16, *xhi, *xlo;
    cudaGetSymbolAddress(&state, g_state);
    cudaGetSymbolAddress(&shi,   g_shi);
    cudaGetSymbolAddress(&slo,   g_slo);
    cudaGetSymbolAddress(&w16,   g_w16);
    cudaGetSymbolAddress(&win16, g_win16);
    cudaGetSymbolAddress(&xhi,   g_xhi);
    cudaGetSymbolAddress(&xlo,   g_xlo);

    EncodeFn enc = get_encode_fn();
    TMaps tm;
    enc2d_box(enc, &tm.shi[0], shi, RES, BATCH, RES * 2ull, 64, 32);
    enc2d_box(enc, &tm.shi[1], (char*)shi + (size_t)BATCH * RES * 2,
              RES, BATCH, RES * 2ull, 64, 32);
    enc2d_box(enc, &tm.slo[0], slo, RES, BATCH, RES * 2ull, 64, 32);
    enc2d_box(enc, &tm.slo[1], (char*)slo + (size_t)BATCH * RES * 2,
              RES, BATCH, RES * 2ull, 64, 32);
    enc2d_box(enc, &tm.w, w16, RES, RES, RES * 2ull, 64, 64);
    enc2d_box(enc, &tm.win, win16, RES, INSZ, RES * 2ull, 64, 64);
    enc3d_x(enc, &tm.xhi, xhi);
    enc3d_x(enc, &tm.xlo, xlo);
    enc_state(enc, &tm.st, state);

    cudaFuncSetAttribute(step_kernel,
                         cudaFuncAttributeMaxDynamicSharedMemorySize,
                         SMEM_TOTAL);

    prep_kernel<<<4096, 256>>>(input, Wres, Win);

    dim3 grid(RES / 64, BATCH / 32);   // (16, 16) = 256 CTAs, ~2 per SM
    for (int t = 0; t < SEQLEN; t++)
        step_kernel<<<grid, 128, SMEM_TOTAL>>>(tm, t);

    output_kernel<<<BATCH, 64>>>(Wout, out);
}

// round 16
// speedup vs baseline: 1.0731x; 1.0731x over previous
#include <cuda_runtime.h>
#include <cuda.h>
#include <cuda_fp16.h>
#include <cstdint>

#define BATCH 512
#define SEQLEN 512
#define INSZ 64
#define RES 1024
#define OUTSZ 64

// ---------------- static device buffers (no allocation allowed) -------------
__device__ float g_state[BATCH * RES];              // fp32 state, in-place
__device__ __half g_shi[2][BATCH * RES];            // state hi (fp16), ping-pong
__device__ __half g_slo[2][BATCH * RES];            // state lo (fp16), ping-pong
__device__ __half g_w16[RES * RES];                 // W_res in fp16
__device__ __half g_win16[INSZ * RES];              // W_in in fp16
__device__ __half g_xhi[BATCH * SEQLEN * INSZ];     // input hi
__device__ __half g_xlo[BATCH * SEQLEN * INSZ];     // input lo

struct TMaps {
    CUtensorMap shi[2];   // fp16, box {64,32}
    CUtensorMap slo[2];   // fp16, box {64,32}
    CUtensorMap w;        // fp16, box {64,64}
    CUtensorMap win;      // fp16, box {64,64}
    CUtensorMap xhi;      // fp16 3D, box {64,1,32}
    CUtensorMap xlo;
    CUtensorMap st;       // fp32, box {64,32}, no swizzle
};

// ---------------- merged prep kernel (ONE launch) ---------------------------
__global__ void prep_kernel(const float* __restrict__ input,
                            const float* __restrict__ Wres,
                            const float* __restrict__ Win) {
    int i = blockIdx.x * blockDim.x + threadIdx.x;
    int stride = gridDim.x * blockDim.x;
    const __half z = __float2half(0.0f);
    for (int k = i; k < BATCH * SEQLEN * INSZ; k += stride) {
        float v = input[k];
        __half h = __float2half(v);
        g_xhi[k] = h;
        g_xlo[k] = __float2half(v - __half2float(h));
        if (k < RES * RES) g_w16[k] = __float2half(Wres[k]);
        if (k < INSZ * RES) g_win16[k] = __float2half(Win[k]);
        if (k < BATCH * RES) {
            g_state[k] = 0.0f;
            g_shi[0][k] = z;
            g_slo[0][k] = z;
        }
    }
}

// ---------------- fast tanh (ex2 + rcp approx; abs err ~1e-6) ---------------
__device__ __forceinline__ float fast_tanhf(float x) {
    float e;
    asm("ex2.approx.f32 %0, %1;" : "=f"(e) : "f"(x * 2.8853900817779268f));
    float r;
    asm("rcp.approx.f32 %0, %1;" : "=f"(r) : "f"(e + 1.0f));
    return fmaf(-2.0f, r, 1.0f);
}

// ---------------- PTX helpers ------------------------------------------------
#define MBARRIER_INIT(addr, cnt) \
    asm volatile("mbarrier.init.shared.b64 [%0], %1;" :: "r"(addr), "r"(cnt) : "memory")

#define MBARRIER_EXPECT_TX(addr, bytes) \
    asm volatile("mbarrier.arrive.expect_tx.shared.b64 _, [%0], %1;" \
                 :: "r"(addr), "r"(bytes) : "memory")

#define MBARRIER_WAIT_PARITY(mbar, par) do {                                   \
    uint32_t _m = (mbar); uint32_t _p = (par); uint32_t _done;                 \
    asm volatile("{\n\t.reg .pred p;\n\t"                                      \
        "mbarrier.try_wait.parity.acquire.cta.shared::cta.b64 p, [%1], %2;\n\t"\
        "selp.b32 %0, 1, 0, p;\n\t}" : "=r"(_done) : "r"(_m), "r"(_p) : "memory"); \
    if (!_done) {                                                              \
        asm volatile("{\n\t.reg .pred P1;\n\tWL_%=:\n\t"                       \
            "mbarrier.try_wait.parity.acquire.cta.shared::cta.b64 P1, [%0], %1, 0x989680;\n\t" \
            "@P1 bra.uni WD_%=;\n\tbra.uni WL_%=;\n\tWD_%=:\n\t}"              \
            :: "r"(_m), "r"(_p) : "memory");                                   \
    }                                                                          \
} while (0)

__device__ __forceinline__ void tma2d(uint32_t dst, const CUtensorMap* m,
                                      int c0, int c1, uint32_t mbar) {
    asm volatile(
        "cp.async.bulk.tensor.2d.shared::cluster.global.tile.mbarrier::complete_tx::bytes "
        "[%0], [%1, {%2, %3}], [%4];"
        :: "r"(dst), "l"(m), "r"(c0), "r"(c1), "r"(mbar) : "memory");
}

__device__ __forceinline__ void tma3d(uint32_t dst, const CUtensorMap* m,
                                      int c0, int c1, int c2, uint32_t mbar) {
    asm volatile(
        "cp.async.bulk.tensor.3d.shared::cluster.global.tile.mbarrier::complete_tx::bytes "
        "[%0], [%1, {%2, %3, %4}], [%5];"
        :: "r"(dst), "l"(m), "r"(c0), "r"(c1), "r"(c2), "r"(mbar) : "memory");
}

// ---------------- step kernel ----------------------------------------------
// Y = Shi@W16 + Slo@W16 + xhi@Win16 + xlo@Win16 (2-product fp16 split).
// r16: K-SPLIT warp partition on the r14 base. 4 warps = 2(M) x 2(K):
// each warp computes its 16-row half for ALL 64 cols over HALF the kf
// slices. LDSM/CTA -25% (no cross-warpN duplication); 16 independent MMA
// chains per warp. Cross-warp K-reduction through retired slot-0 smem at
// the end, then warps 0/1 run the epilogue.
// Tile BM=32 x BN=64, grid (16,16)=256 CTAs, 128 thr, NSLOT=3 ring,
// TMA loader, smem-staged fp32 state epilogue.
#define NIT 9
#define NSLOT 3
#define STAGE_BYTES 32768      // Ahi 8K | Alo 8K | B 16K
#define A_LO_OFF 8192
#define B_OFF    16384
#define ST_OFF   (NSLOT * STAGE_BYTES)          // fp32 state tile 32x64 = 8K
#define SMEM_TOTAL (ST_OFF + 8192)

__device__ __forceinline__ uint32_t sw_off(int row, int colByte) {
    // 128B rows, XOR-swizzled 16B chunks == TMA SW128 atom layout
    return (uint32_t)(row * 128 + ((((colByte >> 4) ^ (row & 7)) << 4) | (colByte & 15)));
}

// NKF = total k16 slices in this block; each warp does NKF/2 of them.
template<int NKF>
__device__ __forceinline__ void do_block(uint32_t base, int lane, int warpM, int warpK,
                                         float (&acch)[8][4], float (&accl)[8][4]) {
    uint32_t fa[2][2][4];   // [buf][hi/lo][regs]
    uint32_t fb[2][4][4];   // [buf][nh 0..3][regs]
    const int kf0 = warpK * (NKF / 2);

    auto ld = [&](int kf, int buf) {
        const int kfl = kf & 3;
        {
            const uint32_t sub = (uint32_t)(kf >> 2) * 4096;   // A half-tiles 4K
            int row = warpM * 16 + (lane & 15);
            int colByte = kfl * 32 + (lane >> 4) * 16;
            uint32_t so = sw_off(row, colByte);
            asm volatile("ldmatrix.sync.aligned.m8n8.x4.shared.b16 {%0,%1,%2,%3}, [%4];"
                : "=r"(fa[buf][0][0]), "=r"(fa[buf][0][1]),
                  "=r"(fa[buf][0][2]), "=r"(fa[buf][0][3])
                : "r"(base + sub + so));
            asm volatile("ldmatrix.sync.aligned.m8n8.x4.shared.b16 {%0,%1,%2,%3}, [%4];"
                : "=r"(fa[buf][1][0]), "=r"(fa[buf][1][1]),
                  "=r"(fa[buf][1][2]), "=r"(fa[buf][1][3])
                : "r"(base + A_LO_OFF + sub + so));
        }
        #pragma unroll
        for (int nh = 0; nh < 4; nh++) {           // all 64 cols = 4 n16 halves
            const uint32_t sub = (uint32_t)(kf >> 2) * 8192;   // B half-tiles 8K
            int krow = kfl * 16 + (lane & 7) + ((lane >> 3) & 1) * 8;
            int colByte = (nh * 16 + (lane >> 4) * 8) * 2;
            asm volatile("ldmatrix.sync.aligned.m8n8.x4.trans.shared.b16 {%0,%1,%2,%3}, [%4];"
                : "=r"(fb[buf][nh][0]), "=r"(fb[buf][nh][1]),
                  "=r"(fb[buf][nh][2]), "=r"(fb[buf][nh][3])
                : "r"(base + B_OFF + sub + sw_off(krow, colByte)));
        }
    };

    ld(kf0, 0);
    #pragma unroll
    for (int i = 0; i < NKF / 2; i++) {
        const int cur = i & 1;
        if (i + 1 < NKF / 2) ld(kf0 + i + 1, cur ^ 1);   // prefetch next frags
        #pragma unroll
        for (int j = 0; j < 8; j++) {              // 8 n8 groups = 64 cols
            uint32_t b0 = fb[cur][j >> 1][(j & 1) * 2];
            uint32_t b1 = fb[cur][j >> 1][(j & 1) * 2 + 1];
            asm volatile(
                "mma.sync.aligned.m16n8k16.row.col.f32.f16.f16.f32 "
                "{%0,%1,%2,%3}, {%4,%5,%6,%7}, {%8,%9}, {%0,%1,%2,%3};"
                : "+f"(acch[j][0]), "+f"(acch[j][1]), "+f"(acch[j][2]), "+f"(acch[j][3])
                : "r"(fa[cur][0][0]), "r"(fa[cur][0][1]),
                  "r"(fa[cur][0][2]), "r"(fa[cur][0][3]), "r"(b0), "r"(b1));
            asm volatile(
                "mma.sync.aligned.m16n8k16.row.col.f32.f16.f16.f32 "
                "{%0,%1,%2,%3}, {%4,%5,%6,%7}, {%8,%9}, {%0,%1,%2,%3};"
                : "+f"(accl[j][0]), "+f"(accl[j][1]), "+f"(accl[j][2]), "+f"(accl[j][3])
                : "r"(fa[cur][1][0]), "r"(fa[cur][1][1]),
                  "r"(fa[cur][1][2]), "r"(fa[cur][1][3]), "r"(b0), "r"(b1));
        }
    }
}

__global__ __launch_bounds__(128) void step_kernel(
    const __grid_constant__ TMaps tm, int t) {
    extern __shared__ __align__(1024) char smem[];
    __shared__ __align__(8) uint64_t s_mbar[NSLOT + 1];   // slots + state

    const int tid  = threadIdx.x;
    const int lane = tid & 31;
    const int warp = tid >> 5;
    const int warpM = warp & 1;     // 2 warps along M (16 rows each)
    const int warpK = warp >> 1;    // 2 warps along K (half the kf slices)
    const int rowBase = blockIdx.y * 32;
    const int colBase = blockIdx.x * 64;
    const int pp = t & 1;

    const uint32_t smem_u32 = (uint32_t)__cvta_generic_to_shared(smem);
    const uint32_t mbar0    = (uint32_t)__cvta_generic_to_shared(s_mbar);

    const CUtensorMap* mShi = &tm.shi[pp];
    const CUtensorMap* mSlo = &tm.slo[pp];

    if (tid == 0) {
        #pragma unroll
        for (int s = 0; s < NSLOT + 1; s++) MBARRIER_INIT(mbar0 + s * 8, 1);
    }
    __syncthreads();

    auto issue = [&](int kk) {
        uint32_t base = smem_u32 + (kk % NSLOT) * STAGE_BYTES;
        uint32_t mb   = mbar0 + (kk % NSLOT) * 8;
        if (kk < 8) {
            int k0 = kk << 7;
            MBARRIER_EXPECT_TX(mb, 32768u);
            tma2d(base,                   mShi, k0,      rowBase, mb);
            tma2d(base + 4096,            mShi, k0 + 64, rowBase, mb);
            tma2d(base + A_LO_OFF,        mSlo, k0,      rowBase, mb);
            tma2d(base + A_LO_OFF + 4096, mSlo, k0 + 64, rowBase, mb);
            tma2d(base + B_OFF,           &tm.w, colBase, k0,      mb);
            tma2d(base + B_OFF + 8192,    &tm.w, colBase, k0 + 64, mb);
        } else {
            MBARRIER_EXPECT_TX(mb, 16384u);
            tma3d(base,            &tm.xhi, 0, t, rowBase, mb);
            tma3d(base + A_LO_OFF, &tm.xlo, 0, t, rowBase, mb);
            tma2d(base + B_OFF,    &tm.win, colBase, 0, mb);
        }
    };

    if (tid == 0) {
        // state tile prefetch (overlaps the whole GEMM)
        MBARRIER_EXPECT_TX(mbar0 + NSLOT * 8, 8192u);
        tma2d(smem_u32 + ST_OFF, &tm.st, colBase, rowBase, mbar0 + NSLOT * 8);
        issue(0); issue(1);
    }

    float acch[8][4], accl[8][4];
    #pragma unroll
    for (int j = 0; j < 8; j++)
        #pragma unroll
        for (int q = 0; q < 4; q++) { acch[j][q] = 0.0f; accl[j][q] = 0.0f; }

    for (int kk = 0; kk < NIT; kk++) {
        __syncthreads();             // all warps done reading slot (kk+2)%NSLOT
        if (tid == 0 && kk + 2 < NIT) issue(kk + 2);
        MBARRIER_WAIT_PARITY(mbar0 + (kk % NSLOT) * 8, (uint32_t)((kk / NSLOT) & 1));

        uint32_t base = smem_u32 + (kk % NSLOT) * STAGE_BYTES;
        if (kk < 8) do_block<8>(base, lane, warpM, warpK, acch, accl);
        else        do_block<4>(base, lane, warpM, warpK, acch, accl);
    }

    // ---- combine hi+lo locally, then cross-warp K reduction -----------------
    float y[8][4];
    #pragma unroll
    for (int j = 0; j < 8; j++)
        #pragma unroll
        for (int q = 0; q < 4; q++) y[j][q] = acch[j][q] + accl[j][q];

    // warps 2,3 (warpK=1) publish partials into retired slot-0 smem
    // (all warps are past kk=6, slot0's last use, due to per-iter syncthreads)
    __syncthreads();
    if (warpK == 1) {
        uint32_t rbase = smem_u32 + warpM * 8192;
        #pragma unroll
        for (int j = 0; j < 8; j++) {
            uint32_t addr = rbase + (uint32_t)(j * 32 + lane) * 16;
            asm volatile("st.shared.v4.f32 [%0], {%1,%2,%3,%4};"
                :: "r"(addr), "f"(y[j][0]), "f"(y[j][1]), "f"(y[j][2]), "f"(y[j][3]));
        }
    }
    __syncthreads();

    if (warpK == 0) {
        uint32_t rbase = smem_u32 + warpM * 8192;
        #pragma unroll
        for (int j = 0; j < 8; j++) {
            float p0, p1, p2, p3;
            uint32_t addr = rbase + (uint32_t)(j * 32 + lane) * 16;
            asm volatile("ld.shared.v4.f32 {%0,%1,%2,%3}, [%4];"
                : "=f"(p0), "=f"(p1), "=f"(p2), "=f"(p3) : "r"(addr));
            y[j][0] += p0; y[j][1] += p1; y[j][2] += p2; y[j][3] += p3;
        }

        // ---- epilogue (warps 0,1): leaky tanh; state from smem copy,
        //      write fp32 state + fp16 hi/lo for next step ----
        MBARRIER_WAIT_PARITY(mbar0 + NSLOT * 8, 0u);
        __half* __restrict__ shiN = g_shi[pp ^ 1];
        __half* __restrict__ sloN = g_slo[pp ^ 1];
        #pragma unroll
        for (int j = 0; j < 8; j++)
            #pragma unroll
            for (int h = 0; h < 2; h++) {
                int rloc = warpM * 16 + (lane >> 2) + 8 * h;      // 0..31
                int cloc = j * 8 + (lane & 3) * 2;                // 0..62
                int row = rowBase + rloc;
                int col = colBase + cloc;
                long long idx = (long long)row * RES + col;
                float y0 = y[j][h * 2 + 0];
                float y1 = y[j][h * 2 + 1];
                float2 sold = *reinterpret_cast<float2*>(
                    smem + ST_OFF + rloc * 256 + cloc * 4);
                float n0 = 0.5f * sold.x + 0.5f * fast_tanhf(y0);
                float n1 = 0.5f * sold.y + 0.5f * fast_tanhf(y1);
                *reinterpret_cast<float2*>(&g_state[idx]) = make_float2(n0, n1);
                __half h0 = __float2half(n0);
                __half h1 = __float2half(n1);
                __half2 hv; hv.x = h0; hv.y = h1;
                __half2 lv;
                lv.x = __float2half(n0 - __half2float(h0));
                lv.y = __float2half(n1 - __half2float(h1));
                *reinterpret_cast<__half2*>(&shiN[idx]) = hv;
                *reinterpret_cast<__half2*>(&sloN[idx]) = lv;
            }
    }
}

// ---------------- output GEMM ----------------------------------------------
__global__ __launch_bounds__(64) void output_kernel(
    const float* __restrict__ Wout, float* __restrict__ out) {
    __shared__ float srow[RES];
    const int b = blockIdx.x;
    const int j = threadIdx.x;
    for (int k = j; k < RES; k += 64) srow[k] = g_state[b * RES + k];
    __syncthreads();
    float sum = 0.0f;
    #pragma unroll 8
    for (int k = 0; k < RES; k++)
        sum = fmaf(srow[k], Wout[k * OUTSZ + j], sum);
    out[b * OUTSZ + j] = sum;
}

// ---------------- host: tensormap construction ------------------------------
typedef CUresult (*EncodeFn)(CUtensorMap*, CUtensorMapDataType, cuuint32_t, void*,
                             const cuuint64_t*, const cuuint64_t*, const cuuint32_t*,
                             const cuuint32_t*, CUtensorMapInterleave, CUtensorMapSwizzle,
                             CUtensorMapL2promotion, CUtensorMapFloatOOBfill);

static EncodeFn get_encode_fn() {
    void* p = nullptr;
#if CUDART_VERSION >= 12050
    cudaDriverEntryPointQueryResult st;
    cudaGetDriverEntryPointByVersion("cuTensorMapEncodeTiled", &p, 12000,
                                     cudaEnableDefault, &st);
#else
    cudaDriverEntryPointQueryResult st;
    cudaGetDriverEntryPoint("cuTensorMapEncodeTiled", &p, cudaEnableDefault, &st);
#endif
    return (EncodeFn)p;
}

static void enc2d_box(EncodeFn f, CUtensorMap* m, void* ptr,
                      uint64_t d0, uint64_t d1, uint64_t stride1B,
                      uint32_t b0, uint32_t b1) {
    cuuint64_t dims[2] = {d0, d1};
    cuuint64_t strides[1] = {stride1B};
    cuuint32_t box[2] = {b0, b1};
    cuuint32_t es[2] = {1, 1};
    f(m, CU_TENSOR_MAP_DATA_TYPE_FLOAT16, 2, ptr, dims, strides, box, es,
      CU_TENSOR_MAP_INTERLEAVE_NONE, CU_TENSOR_MAP_SWIZZLE_128B,
      CU_TENSOR_MAP_L2_PROMOTION_L2_128B, CU_TENSOR_MAP_FLOAT_OOB_FILL_NONE);
}

static void enc_state(EncodeFn f, CUtensorMap* m, void* ptr) {
    cuuint64_t dims[2] = {RES, BATCH};
    cuuint64_t strides[1] = {RES * 4ull};
    cuuint32_t box[2] = {64, 32};
    cuuint32_t es[2] = {1, 1};
    f(m, CU_TENSOR_MAP_DATA_TYPE_FLOAT32, 2, ptr, dims, strides, box, es,
      CU_TENSOR_MAP_INTERLEAVE_NONE, CU_TENSOR_MAP_SWIZZLE_NONE,
      CU_TENSOR_MAP_L2_PROMOTION_L2_128B, CU_TENSOR_MAP_FLOAT_OOB_FILL_NONE);
}

static void enc3d_x(EncodeFn f, CUtensorMap* m, void* ptr) {
    cuuint64_t dims[3] = {INSZ, SEQLEN, BATCH};
    cuuint64_t strides[2] = {INSZ * 2ull, (uint64_t)SEQLEN * INSZ * 2ull};
    cuuint32_t box[3] = {64, 1, 32};
    cuuint32_t es[3] = {1, 1, 1};
    f(m, CU_TENSOR_MAP_DATA_TYPE_FLOAT16, 3, ptr, dims, strides, box, es,
      CU_TENSOR_MAP_INTERLEAVE_NONE, CU_TENSOR_MAP_SWIZZLE_128B,
      CU_TENSOR_MAP_L2_PROMOTION_L2_128B, CU_TENSOR_MAP_FLOAT_OOB_FILL_NONE);
}

// ---------------- launch ----------------------------------------------------
extern "C" void kernel_launch(void* const* d_in, const int* in_sizes, int n_in,
                              void* d_out, int out_size) {
    const float* input = (const float*)d_in[0];   // [512,512,64]
    const float* Wres  = (const float*)d_in[1];   // [1024,1024]
    const float* Win   = (const float*)d_in[2];   // [64,1024]
    const float* Wout  = (const float*)d_in[3];   // [1024,64]
    float* out = (float*)d_out;

    void *state, *shi, *slo, *w16, *win16, *xhi, *xlo;
    cudaGetSymbolAddress(&state, g_state);
    cudaGetSymbolAddress(&shi,   g_shi);
    cudaGetSymbolAddress(&slo,   g_slo);
    cudaGetSymbolAddress(&w16,   g_w16);
    cudaGetSymbolAddress(&win16, g_win16);
    cudaGetSymbolAddress(&xhi,   g_xhi);
    cudaGetSymbolAddress(&xlo,   g_xlo);

    EncodeFn enc = get_encode_fn();
    TMaps tm;
    enc2d_box(enc, &tm.shi[0], shi, RES, BATCH, RES * 2ull, 64, 32);
    enc2d_box(enc, &tm.shi[1], (char*)shi + (size_t)BATCH * RES * 2,
              RES, BATCH, RES * 2ull, 64, 32);
    enc2d_box(enc, &tm.slo[0], slo, RES, BATCH, RES * 2ull, 64, 32);
    enc2d_box(enc, &tm.slo[1], (char*)slo + (size_t)BATCH * RES * 2,
              RES, BATCH, RES * 2ull, 64, 32);
    enc2d_box(enc, &tm.w, w16, RES, RES, RES * 2ull, 64, 64);
    enc2d_box(enc, &tm.win, win16, RES, INSZ, RES * 2ull, 64, 64);
    enc3d_x(enc, &tm.xhi, xhi);
    enc3d_x(enc, &tm.xlo, xlo);
    enc_state(enc, &tm.st, state);

    cudaFuncSetAttribute(step_kernel,
                         cudaFuncAttributeMaxDynamicSharedMemorySize,
                         SMEM_TOTAL);

    prep_kernel<<<4096, 256>>>(input, Wres, Win);

    dim3 grid(RES / 64, BATCH / 32);   // (16, 16) = 256 CTAs, ~2 per SM
    for (int t = 0; t < SEQLEN; t++)
        step_kernel<<<grid, 128, SMEM_TOTAL>>>(tm, t);

    output_kernel<<<BATCH, 64>>>(Wout, out);
}